// round 9
// baseline (speedup 1.0000x reference)
#include <cuda_runtime.h>
#include <math.h>

// Problem constants
#define BATCH 4
#define SEQ   2048
#define CDIM  1024
#define NH    16
#define HD    64
#define ROWS  (BATCH*SEQ)      // 8192
#define QKVC  (3*CDIM)         // 3072

// Scratch (allocation-free rule: __device__ globals)
__device__ float g_qkv[(size_t)ROWS * QKVC];  // q|k|v (tf32-rounded)
__device__ float g_y[(size_t)ROWS * CDIM];    // attn out (tf32-rounded)
__device__ float g_xc[(size_t)ROWS * CDIM];   // x,  tf32-rounded
__device__ float g_wa[(size_t)CDIM * QKVC];   // W_attn, tf32-rounded
__device__ float g_wp[(size_t)CDIM * CDIM];   // W_proj, tf32-rounded

__device__ __forceinline__ unsigned f2tf32(float f) {
    unsigned r;
    asm("cvt.rna.tf32.f32 %0, %1;" : "=r"(r) : "f"(f));
    return r;
}
__device__ __forceinline__ float tf32r(float f) {
    return __uint_as_float(f2tf32(f));
}

__device__ __forceinline__ void mma_tf32(float c[4], unsigned a0, unsigned a1,
                                         unsigned a2, unsigned a3,
                                         unsigned b0, unsigned b1) {
    asm volatile(
        "mma.sync.aligned.m16n8k8.row.col.f32.tf32.tf32.f32 "
        "{%0,%1,%2,%3}, {%4,%5,%6,%7}, {%8,%9}, {%0,%1,%2,%3};\n"
        : "+f"(c[0]), "+f"(c[1]), "+f"(c[2]), "+f"(c[3])
        : "r"(a0), "r"(a1), "r"(a2), "r"(a3), "r"(b0), "r"(b1));
}

__device__ __forceinline__ void cp16(unsigned smem_addr, const void* gptr) {
    asm volatile("cp.async.cg.shared.global [%0], [%1], 16;\n"
                 :: "r"(smem_addr), "l"(gptr));
}
__device__ __forceinline__ void cp_commit() {
    asm volatile("cp.async.commit_group;\n" ::);
}

// ---------------------------------------------------------------------------
// Pre-pass: round fp32 array to tf32 bit pattern (vectorized, coalesced).
// ---------------------------------------------------------------------------
__global__ __launch_bounds__(256)
void round_tf32(const float* __restrict__ in, float* __restrict__ out, int n4)
{
    int i = blockIdx.x * blockDim.x + threadIdx.x;
    if (i < n4) {
        float4 v = ((const float4*)in)[i];
        v.x = tf32r(v.x); v.y = tf32r(v.y); v.z = tf32r(v.z); v.w = tf32r(v.w);
        ((float4*)out)[i] = v;
    }
}

// ---------------------------------------------------------------------------
// tf32 tensor-core GEMM + bias. Inputs pre-rounded to tf32 bits.
// Block 128x128x16, 128 threads = 4 warps (2x2), WARP TILE 64x64:
// per warp per k-tile 64 LDS.32 vs 64 MMA -> tensor-pipe bound.
// 3-stage cp.async pipeline, one __syncthreads per k-tile.
// ---------------------------------------------------------------------------
#define AS_STRIDE 20            // 16 + 4 pad
#define BS_STRIDE 136           // 128 + 8 pad
#define AS_SZ (128 * AS_STRIDE) // floats per stage
#define BS_SZ (16 * BS_STRIDE)
#define GEMM_SMEM (3 * (AS_SZ + BS_SZ) * 4)

__global__ __launch_bounds__(128)
void gemm_tf32(const float* __restrict__ A, const float* __restrict__ B,
               const float* __restrict__ bias, float* __restrict__ C,
               int M, int N, int K, int roundOut)
{
    extern __shared__ float sm[];
    float* Asm = sm;                 // [3][AS_SZ]
    float* Bsm = sm + 3 * AS_SZ;     // [3][BS_SZ]

    const int tid   = threadIdx.x;
    const int wid   = tid >> 5;
    const int lane  = tid & 31;
    const int warpM = wid >> 1;          // 0..1 -> 64 rows
    const int warpN = wid & 1;           // 0..1 -> 64 cols
    const int group = lane >> 2;         // 0..7
    const int tig   = lane & 3;          // 0..3

    const int rowBase = blockIdx.y * 128;
    const int colBase = blockIdx.x * 128;

    // loaders (128 threads): A 128x16 = 512 chunks, B 16x128 = 512 chunks
    const int aRow = tid >> 2;           // 0..31 (+32k)
    const int aC4  = tid & 3;
    const int bRow = tid >> 5;           // 0..3 (+4k)
    const int bC4  = tid & 31;

    const unsigned sAb = (unsigned)__cvta_generic_to_shared(Asm);
    const unsigned sBb = (unsigned)__cvta_generic_to_shared(Bsm);

    float acc[4][8][4];
#pragma unroll
    for (int mt = 0; mt < 4; mt++)
#pragma unroll
        for (int nt = 0; nt < 8; nt++)
#pragma unroll
            for (int i = 0; i < 4; i++) acc[mt][nt][i] = 0.f;

    const int nTiles = K >> 4;

    auto loadTile = [&](int s, int k0) {
        unsigned sA = sAb + s * AS_SZ * 4;
        unsigned sB = sBb + s * BS_SZ * 4;
#pragma unroll
        for (int i = 0; i < 4; i++) {
            int row = aRow + i * 32;
            cp16(sA + (row * AS_STRIDE + aC4 * 4) * 4,
                 A + (size_t)(rowBase + row) * K + k0 + aC4 * 4);
        }
#pragma unroll
        for (int i = 0; i < 4; i++) {
            int row = bRow + i * 4;
            cp16(sB + (row * BS_STRIDE + bC4 * 4) * 4,
                 B + (size_t)(k0 + row) * N + colBase + bC4 * 4);
        }
    };

    // prologue: 2 stages in flight
    loadTile(0, 0);  cp_commit();
    loadTile(1, 16); cp_commit();

    for (int kt = 0; kt < nTiles; kt++) {
        asm volatile("cp.async.wait_group 1;\n" ::);   // stage kt ready
        __syncthreads();
        if (kt + 2 < nTiles) loadTile((kt + 2) % 3, (kt + 2) << 4);
        cp_commit();                                    // always (tail-safe)

        const int st = kt % 3;
        const unsigned* as = (const unsigned*)(Asm + st * AS_SZ);
        const unsigned* bs = (const unsigned*)(Bsm + st * BS_SZ);

#pragma unroll
        for (int ks = 0; ks < 2; ks++) {
            const int kb = ks * 8;
            unsigned af[4][4];
#pragma unroll
            for (int mt = 0; mt < 4; mt++) {
                int r = warpM * 64 + mt * 16 + group;
                af[mt][0] = as[(r + 0) * AS_STRIDE + kb + tig];
                af[mt][1] = as[(r + 8) * AS_STRIDE + kb + tig];
                af[mt][2] = as[(r + 0) * AS_STRIDE + kb + tig + 4];
                af[mt][3] = as[(r + 8) * AS_STRIDE + kb + tig + 4];
            }
            unsigned bf[8][2];
#pragma unroll
            for (int nt = 0; nt < 8; nt++) {
                int c = warpN * 64 + nt * 8 + group;
                bf[nt][0] = bs[(kb + tig + 0) * BS_STRIDE + c];
                bf[nt][1] = bs[(kb + tig + 4) * BS_STRIDE + c];
            }
#pragma unroll
            for (int mt = 0; mt < 4; mt++)
#pragma unroll
                for (int nt = 0; nt < 8; nt++)
                    mma_tf32(acc[mt][nt], af[mt][0], af[mt][1], af[mt][2],
                             af[mt][3], bf[nt][0], bf[nt][1]);
        }
        // no trailing sync: next iteration's sync protects slot reuse
    }

#pragma unroll
    for (int mt = 0; mt < 4; mt++) {
        int r0 = rowBase + warpM * 64 + mt * 16 + group;
#pragma unroll
        for (int nt = 0; nt < 8; nt++) {
            int c = colBase + warpN * 64 + nt * 8 + 2 * tig;
            float b0 = bias[c], b1 = bias[c + 1];
            float o00 = acc[mt][nt][0] + b0, o01 = acc[mt][nt][1] + b1;
            float o10 = acc[mt][nt][2] + b0, o11 = acc[mt][nt][3] + b1;
            if (roundOut) {
                o00 = tf32r(o00); o01 = tf32r(o01);
                o10 = tf32r(o10); o11 = tf32r(o11);
            }
            *(float2*)&C[(size_t)(r0 + 0) * N + c] = make_float2(o00, o01);
            *(float2*)&C[(size_t)(r0 + 8) * N + c] = make_float2(o10, o11);
        }
    }
}

// ---------------------------------------------------------------------------
// Tensor-core flash attention (unchanged from R7 pass).
// ---------------------------------------------------------------------------
#define BQ 128
#define BKV 64
#define KS_STRIDE 68
#define VS_STRIDE 72
#define PS_STRIDE 68
#define KS_SZ (BKV * KS_STRIDE)
#define VS_SZ (BKV * VS_STRIDE)
#define ATTN_SMEM ((2*KS_SZ + 2*VS_SZ + BQ*PS_STRIDE) * 4)

__global__ __launch_bounds__(256)
void attn_tc(const float* __restrict__ qkv, float* __restrict__ y)
{
    extern __shared__ unsigned smem[];
    unsigned* Ks = smem;                    // [2][KS_SZ]
    unsigned* Vs = smem + 2 * KS_SZ;        // [2][VS_SZ]
    unsigned* Ps = Vs + 2 * VS_SZ;          // [BQ][PS_STRIDE]

    const int q0 = blockIdx.x * BQ;
    const int h  = blockIdx.y;
    const int b  = blockIdx.z;

    const int tid  = threadIdx.x;
    const int w    = tid >> 5;
    const int lane = tid & 31;
    const int g    = lane >> 2;
    const int t    = lane & 3;

    const size_t base = (size_t)b * SEQ * QKVC;
    const int hoff = h * HD;
    const int rowA = q0 + w * 16 + g;

    const unsigned ksb = (unsigned)__cvta_generic_to_shared(Ks);
    const unsigned vsb = (unsigned)__cvta_generic_to_shared(Vs);

    auto loadKV = [&](int s, int k0) {
        unsigned kb_ = ksb + s * KS_SZ * 4;
        unsigned vb_ = vsb + s * VS_SZ * 4;
#pragma unroll
        for (int i = 0; i < 4; i++) {
            int idx = tid + i * 256;
            int row = idx >> 4, c4 = idx & 15;
            const float* gk = qkv + base + (size_t)(k0 + row) * QKVC + hoff + c4 * 4;
            cp16(kb_ + (row * KS_STRIDE + c4 * 4) * 4, gk + CDIM);
            cp16(vb_ + (row * VS_STRIDE + c4 * 4) * 4, gk + 2 * CDIM);
        }
    };

    // Q fragments (pre-rounded tf32; *0.125f is exp-only, mantissa-exact)
    unsigned qa[8][4];
    {
        const float* Q0 = qkv + base + (size_t)rowA * QKVC + hoff;
        const float* Q8 = Q0 + (size_t)8 * QKVC;
#pragma unroll
        for (int kb = 0; kb < 8; kb++) {
            qa[kb][0] = __float_as_uint(Q0[kb * 8 + t] * 0.125f);
            qa[kb][1] = __float_as_uint(Q8[kb * 8 + t] * 0.125f);
            qa[kb][2] = __float_as_uint(Q0[kb * 8 + t + 4] * 0.125f);
            qa[kb][3] = __float_as_uint(Q8[kb * 8 + t + 4] * 0.125f);
        }
    }

    float O[8][4];
#pragma unroll
    for (int nt = 0; nt < 8; nt++)
#pragma unroll
        for (int i = 0; i < 4; i++) O[nt][i] = 0.f;
    float m0 = -INFINITY, m1 = -INFINITY, l0 = 0.f, l1 = 0.f;

    const int ntiles = (q0 + BQ) >> 6;

    loadKV(0, 0); cp_commit();

    for (int kt = 0; kt < ntiles; kt++) {
        const int k0 = kt << 6;
        asm volatile("cp.async.wait_group 0;\n" ::);   // tile kt in smem
        __syncthreads();
        if (kt + 1 < ntiles) loadKV((kt + 1) & 1, (kt + 1) << 6);
        cp_commit();

        // Fully-masked tile for this warp => exact identity update: skip.
        if (k0 > q0 + w * 16 + 15) continue;

        const unsigned* ks_ = Ks + (kt & 1) * KS_SZ;
        const unsigned* vs_ = Vs + (kt & 1) * VS_SZ;

        float S[8][4];
#pragma unroll
        for (int nt = 0; nt < 8; nt++)
#pragma unroll
            for (int i = 0; i < 4; i++) S[nt][i] = 0.f;

#pragma unroll
        for (int kb = 0; kb < 8; kb++) {
#pragma unroll
            for (int nt = 0; nt < 8; nt++) {
                const unsigned* kr = &ks_[(nt * 8 + g) * KS_STRIDE + kb * 8 + t];
                mma_tf32(S[nt], qa[kb][0], qa[kb][1], qa[kb][2], qa[kb][3],
                         kr[0], kr[4]);
            }
        }

        if (k0 + BKV - 1 > q0 + w * 16) {
#pragma unroll
            for (int nt = 0; nt < 8; nt++) {
                int col = k0 + nt * 8 + 2 * t;
                if (col > rowA)     S[nt][0] = -INFINITY;
                if (col + 1 > rowA) S[nt][1] = -INFINITY;
                if (col > rowA + 8)     S[nt][2] = -INFINITY;
                if (col + 1 > rowA + 8) S[nt][3] = -INFINITY;
            }
        }

        float mt0 = -INFINITY, mt1 = -INFINITY;
#pragma unroll
        for (int nt = 0; nt < 8; nt++) {
            mt0 = fmaxf(mt0, fmaxf(S[nt][0], S[nt][1]));
            mt1 = fmaxf(mt1, fmaxf(S[nt][2], S[nt][3]));
        }
#pragma unroll
        for (int off = 1; off < 4; off <<= 1) {
            mt0 = fmaxf(mt0, __shfl_xor_sync(0xffffffffu, mt0, off));
            mt1 = fmaxf(mt1, __shfl_xor_sync(0xffffffffu, mt1, off));
        }
        float mn0 = fmaxf(m0, mt0), mn1 = fmaxf(m1, mt1);
        float al0 = __expf(m0 - mn0), al1 = __expf(m1 - mn1);
        m0 = mn0; m1 = mn1;

        float ls0 = 0.f, ls1 = 0.f;
        unsigned* p0 = &Ps[(w * 16 + g) * PS_STRIDE + 2 * t];
        unsigned* p1 = p0 + 8 * PS_STRIDE;
#pragma unroll
        for (int nt = 0; nt < 8; nt++) {
            float e00 = __expf(S[nt][0] - mn0);
            float e01 = __expf(S[nt][1] - mn0);
            float e10 = __expf(S[nt][2] - mn1);
            float e11 = __expf(S[nt][3] - mn1);
            ls0 += e00 + e01;
            ls1 += e10 + e11;
            *(uint2*)&p0[nt * 8] = make_uint2(f2tf32(e00), f2tf32(e01));
            *(uint2*)&p1[nt * 8] = make_uint2(f2tf32(e10), f2tf32(e11));
        }
#pragma unroll
        for (int off = 1; off < 4; off <<= 1) {
            ls0 += __shfl_xor_sync(0xffffffffu, ls0, off);
            ls1 += __shfl_xor_sync(0xffffffffu, ls1, off);
        }
        l0 = l0 * al0 + ls0;
        l1 = l1 * al1 + ls1;
#pragma unroll
        for (int nt = 0; nt < 8; nt++) {
            O[nt][0] *= al0; O[nt][1] *= al0;
            O[nt][2] *= al1; O[nt][3] *= al1;
        }
        __syncwarp();

        const unsigned* pr0 = &Ps[(w * 16 + g) * PS_STRIDE];
        const unsigned* pr8 = pr0 + 8 * PS_STRIDE;
#pragma unroll
        for (int kb = 0; kb < 8; kb++) {
            unsigned pa0 = pr0[kb * 8 + t];
            unsigned pa1 = pr8[kb * 8 + t];
            unsigned pa2 = pr0[kb * 8 + t + 4];
            unsigned pa3 = pr8[kb * 8 + t + 4];
#pragma unroll
            for (int nt = 0; nt < 8; nt++) {
                const unsigned* vr = &vs_[(kb * 8 + t) * VS_STRIDE + nt * 8 + g];
                mma_tf32(O[nt], pa0, pa1, pa2, pa3, vr[0], vr[4 * VS_STRIDE]);
            }
        }
    }

    // normalize + write tf32-rounded (proj gemm consumes raw bits)
    float inv0 = 1.f / l0, inv1 = 1.f / l1;
    float* y0 = y + ((size_t)b * SEQ + rowA) * CDIM + hoff;
    float* y1 = y0 + (size_t)8 * CDIM;
#pragma unroll
    for (int nt = 0; nt < 8; nt++) {
        *(float2*)&y0[nt * 8 + 2 * t] =
            make_float2(tf32r(O[nt][0] * inv0), tf32r(O[nt][1] * inv0));
        *(float2*)&y1[nt * 8 + 2 * t] =
            make_float2(tf32r(O[nt][2] * inv1), tf32r(O[nt][3] * inv1));
    }
}

// ---------------------------------------------------------------------------
extern "C" void kernel_launch(void* const* d_in, const int* in_sizes, int n_in,
                              void* d_out, int out_size)
{
    const float* x      = (const float*)d_in[0];
    const float* W_attn = (const float*)d_in[1];
    const float* b_attn = (const float*)d_in[2];
    const float* W_proj = (const float*)d_in[3];
    const float* b_proj = (const float*)d_in[4];
    float* out = (float*)d_out;

    float *qkv, *y, *xc, *wa, *wp;
    cudaGetSymbolAddress((void**)&qkv, g_qkv);
    cudaGetSymbolAddress((void**)&y,   g_y);
    cudaGetSymbolAddress((void**)&xc,  g_xc);
    cudaGetSymbolAddress((void**)&wa,  g_wa);
    cudaGetSymbolAddress((void**)&wp,  g_wp);

    cudaFuncSetAttribute(gemm_tf32, cudaFuncAttributeMaxDynamicSharedMemorySize,
                         GEMM_SMEM);
    cudaFuncSetAttribute(attn_tc, cudaFuncAttributeMaxDynamicSharedMemorySize,
                         ATTN_SMEM);

    // 0) pre-round operands to tf32 bit patterns
    {
        int n4x = ROWS * CDIM / 4;
        int n4a = CDIM * QKVC / 4;
        int n4p = CDIM * CDIM / 4;
        round_tf32<<<(n4x + 255) / 256, 256>>>(x, xc, n4x);
        round_tf32<<<(n4a + 255) / 256, 256>>>(W_attn, wa, n4a);
        round_tf32<<<(n4p + 255) / 256, 256>>>(W_proj, wp, n4p);
    }

    // 1) qkv = xc @ wa + b_attn  (output tf32-rounded)   [8192,3072]
    gemm_tf32<<<dim3(QKVC / 128, ROWS / 128), 128, GEMM_SMEM>>>(
        xc, wa, b_attn, qkv, ROWS, QKVC, CDIM, 1);
    // 2) attention -> y (tf32-rounded)                   [8192,1024]
    attn_tc<<<dim3(SEQ / BQ, NH, BATCH), 256, ATTN_SMEM>>>(qkv, y);
    // 3) out = y @ wp + b_proj  (full fp32 output)       [8192,1024]
    gemm_tf32<<<dim3(CDIM / 128, ROWS / 128), 128, GEMM_SMEM>>>(
        y, wp, b_proj, out, ROWS, CDIM, CDIM, 0);
}

// round 11
// speedup vs baseline: 1.6029x; 1.6029x over previous
#include <cuda_runtime.h>
#include <cuda_fp16.h>
#include <math.h>

// Problem constants
#define BATCH 4
#define SEQ   2048
#define CDIM  1024
#define NH    16
#define HD    64
#define ROWS  (BATCH*SEQ)      // 8192
#define QKVC  (3*CDIM)         // 3072

// Scratch (allocation-free rule: __device__ globals)
__device__ __half g_qkvh[(size_t)ROWS * 2 * CDIM];   // Q|K rows, half
__device__ __half g_vT[(size_t)BATCH * NH * HD * SEQ]; // V transposed [b][h][d][t]
__device__ __half g_xh[(size_t)ROWS * CDIM];          // x as half
__device__ __half g_waT[(size_t)QKVC * CDIM];         // W_attn^T [N][K]
__device__ __half g_wpT[(size_t)CDIM * CDIM];         // W_proj^T [N][K]
__device__ __half g_yh[(size_t)ROWS * CDIM];          // attn out, half

__device__ __forceinline__ void mma_f16(float c[4], unsigned a0, unsigned a1,
                                        unsigned a2, unsigned a3,
                                        unsigned b0, unsigned b1) {
    asm volatile(
        "mma.sync.aligned.m16n8k16.row.col.f32.f16.f16.f32 "
        "{%0,%1,%2,%3}, {%4,%5,%6,%7}, {%8,%9}, {%0,%1,%2,%3};\n"
        : "+f"(c[0]), "+f"(c[1]), "+f"(c[2]), "+f"(c[3])
        : "r"(a0), "r"(a1), "r"(a2), "r"(a3), "r"(b0), "r"(b1));
}

__device__ __forceinline__ void cp16(unsigned smem_addr, const void* gptr) {
    asm volatile("cp.async.cg.shared.global [%0], [%1], 16;\n"
                 :: "r"(smem_addr), "l"(gptr));
}
__device__ __forceinline__ void cp_commit() {
    asm volatile("cp.async.commit_group;\n" ::);
}
__device__ __forceinline__ unsigned h2u(__half2 h) { return *(unsigned*)&h; }
__device__ __forceinline__ unsigned hmul2u(unsigned a, unsigned s) {
    __half2 r = __hmul2(*(__half2*)&a, *(__half2*)&s);
    return *(unsigned*)&r;
}

// ---------------------------------------------------------------------------
// Pre-pass 1: fp32 -> half, contiguous (float4 -> 4 halves).
// ---------------------------------------------------------------------------
__global__ __launch_bounds__(256)
void conv_half(const float* __restrict__ in, __half* __restrict__ out, int n4)
{
    int i = blockIdx.x * blockDim.x + threadIdx.x;
    if (i < n4) {
        float4 v = ((const float4*)in)[i];
        __half2 lo = __floats2half2_rn(v.x, v.y);
        __half2 hi = __floats2half2_rn(v.z, v.w);
        ((uint2*)out)[i] = make_uint2(h2u(lo), h2u(hi));
    }
}

// ---------------------------------------------------------------------------
// Pre-pass 2: transpose + convert. in [K][N] f32 -> out [N][K] half.
// 32x32 tiles, 32x8 threads.
// ---------------------------------------------------------------------------
__global__ __launch_bounds__(256)
void transpose_h(const float* __restrict__ in, __half* __restrict__ out,
                 int K, int N)
{
    __shared__ float t[32][33];
    const int n0 = blockIdx.x * 32, k0 = blockIdx.y * 32;
    const int tx = threadIdx.x, ty = threadIdx.y;
#pragma unroll
    for (int i = 0; i < 4; i++)
        t[ty + 8 * i][tx] = in[(size_t)(k0 + ty + 8 * i) * N + n0 + tx];
    __syncthreads();
#pragma unroll
    for (int i = 0; i < 4; i++)
        out[(size_t)(n0 + ty + 8 * i) * K + k0 + tx] =
            __float2half_rn(t[tx][ty + 8 * i]);
}

// ---------------------------------------------------------------------------
// fp16 tensor-core GEMM + bias. A [M][K] half row-major, Bt [N][K] half
// (both K-major). Block 128x128x16, 256 thr = 8 warps (2x4), warp 64x32.
// m16n8k16, 3-stage cp.async, one __syncthreads per k-tile.
// Stride 12 half2/row: lane bank = 4g+t (bijective, conflict-free).
// mode 0: f32 out to Cf (ld N). mode 1: cols<2048 -> half qkvh (ld 2048);
//         cols>=2048 -> half vT transposed [b][h][d][t].
// ---------------------------------------------------------------------------
#define AH_STRIDE 12                 // half2 units per row (8 data + 4 pad)
#define AH_SZ (128 * AH_STRIDE)      // unsigned units per stage (per operand)
#define GEMM_SMEM_H (3 * 2 * AH_SZ * 4)

__global__ __launch_bounds__(256)
void gemm_h(const __half* __restrict__ A, const __half* __restrict__ Bt,
            const float* __restrict__ bias, float* __restrict__ Cf,
            __half* __restrict__ qkvh, __half* __restrict__ vT,
            int M, int N, int K, int mode)
{
    extern __shared__ unsigned smh[];
    unsigned* Asm = smh;                 // [3][AH_SZ]
    unsigned* Bsm = smh + 3 * AH_SZ;     // [3][AH_SZ]

    const int tid   = threadIdx.x;
    const int wid   = tid >> 5;
    const int lane  = tid & 31;
    const int warpM = wid >> 2;          // 0..1
    const int warpN = wid & 3;           // 0..3
    const int g     = lane >> 2;         // 0..7
    const int t     = lane & 3;          // 0..3

    const int rowBase = blockIdx.y * 128;
    const int colBase = blockIdx.x * 128;

    // loader: 256 threads, 1 cp16 for A + 1 for B per tile
    const int ldRow = tid >> 1;          // 0..127
    const int ldC   = tid & 1;           // which 8-half chunk

    const unsigned sAb = (unsigned)__cvta_generic_to_shared(Asm);
    const unsigned sBb = (unsigned)__cvta_generic_to_shared(Bsm);

    float acc[4][4][4];
#pragma unroll
    for (int mt = 0; mt < 4; mt++)
#pragma unroll
        for (int nt = 0; nt < 4; nt++)
#pragma unroll
            for (int i = 0; i < 4; i++) acc[mt][nt][i] = 0.f;

    const int nTiles = K >> 4;

    auto loadTile = [&](int s, int k0) {
        cp16(sAb + (s * AH_SZ + ldRow * AH_STRIDE + 4 * ldC) * 4,
             A + (size_t)(rowBase + ldRow) * K + k0 + 8 * ldC);
        cp16(sBb + (s * AH_SZ + ldRow * AH_STRIDE + 4 * ldC) * 4,
             Bt + (size_t)(colBase + ldRow) * K + k0 + 8 * ldC);
    };

    loadTile(0, 0);  cp_commit();
    loadTile(1, 16); cp_commit();

    for (int kt = 0; kt < nTiles; kt++) {
        asm volatile("cp.async.wait_group 1;\n" ::);
        __syncthreads();
        if (kt + 2 < nTiles) loadTile((kt + 2) % 3, (kt + 2) << 4);
        cp_commit();

        const unsigned* as = Asm + (kt % 3) * AH_SZ;
        const unsigned* bs = Bsm + (kt % 3) * AH_SZ;

        unsigned af[4][4];
#pragma unroll
        for (int mt = 0; mt < 4; mt++) {
            int r = warpM * 64 + mt * 16 + g;
            af[mt][0] = as[(r + 0) * AH_STRIDE + t];
            af[mt][1] = as[(r + 8) * AH_STRIDE + t];
            af[mt][2] = as[(r + 0) * AH_STRIDE + t + 4];
            af[mt][3] = as[(r + 8) * AH_STRIDE + t + 4];
        }
        unsigned bf[4][2];
#pragma unroll
        for (int nt = 0; nt < 4; nt++) {
            int c = warpN * 32 + nt * 8 + g;
            bf[nt][0] = bs[c * AH_STRIDE + t];
            bf[nt][1] = bs[c * AH_STRIDE + t + 4];
        }
#pragma unroll
        for (int mt = 0; mt < 4; mt++)
#pragma unroll
            for (int nt = 0; nt < 4; nt++)
                mma_f16(acc[mt][nt], af[mt][0], af[mt][1], af[mt][2],
                        af[mt][3], bf[nt][0], bf[nt][1]);
    }

#pragma unroll
    for (int mt = 0; mt < 4; mt++) {
        int r0 = rowBase + warpM * 64 + mt * 16 + g;
#pragma unroll
        for (int nt = 0; nt < 4; nt++) {
            int c = colBase + warpN * 32 + nt * 8 + 2 * t;
            float b0 = bias[c], b1 = bias[c + 1];
            float o00 = acc[mt][nt][0] + b0, o01 = acc[mt][nt][1] + b1;
            float o10 = acc[mt][nt][2] + b0, o11 = acc[mt][nt][3] + b1;
            if (mode == 0) {
                *(float2*)&Cf[(size_t)(r0 + 0) * N + c] = make_float2(o00, o01);
                *(float2*)&Cf[(size_t)(r0 + 8) * N + c] = make_float2(o10, o11);
            } else if (c < 2 * CDIM) {
                // Q|K rows, half, row stride 2048
                *(unsigned*)&qkvh[(size_t)(r0 + 0) * 2048 + c] =
                    h2u(__floats2half2_rn(o00, o01));
                *(unsigned*)&qkvh[(size_t)(r0 + 8) * 2048 + c] =
                    h2u(__floats2half2_rn(o10, o11));
            } else {
                // V -> transposed [b][h][d][t]
                int hh = (c - 2 * CDIM) >> 6, d = (c - 2 * CDIM) & 63;
                int bb = r0 >> 11, tt = r0 & 2047;
                size_t rb = ((size_t)bb * NH + hh) * HD;
                vT[(rb + d    ) * SEQ + tt    ] = __float2half_rn(o00);
                vT[(rb + d + 1) * SEQ + tt    ] = __float2half_rn(o01);
                vT[(rb + d    ) * SEQ + tt + 8] = __float2half_rn(o10);
                vT[(rb + d + 1) * SEQ + tt + 8] = __float2half_rn(o11);
            }
        }
    }
}

// ---------------------------------------------------------------------------
// fp16 tensor-core flash attention. Q,K from qkvh rows; V from vT (already
// transposed). m16n8k16: HD=64 -> 4 k-steps for S, BKV=64 -> 4 for PV.
// Smem stride 36 half2 -> lane bank 4g+t (conflict-free).
// ---------------------------------------------------------------------------
#define BQ 128
#define BKV 64
#define TS_H 36                       // half2 stride (32 data + 4 pad)
#define KV_SZ (BKV * TS_H)            // unsigned units
#define ATTN_SMEM_H ((2 * KV_SZ + 2 * KV_SZ + BQ * TS_H) * 4)

__global__ __launch_bounds__(256)
void attn_h(const __half* __restrict__ qkvh, const __half* __restrict__ vT,
            __half* __restrict__ yh)
{
    extern __shared__ unsigned smem[];
    unsigned* Ks = smem;                    // [2][KV_SZ]
    unsigned* Vs = smem + 2 * KV_SZ;        // [2][KV_SZ]
    unsigned* Ps = Vs + 2 * KV_SZ;          // [BQ][TS_H]

    const int q0 = blockIdx.x * BQ;
    const int h  = blockIdx.y;
    const int b  = blockIdx.z;

    const int tid  = threadIdx.x;
    const int w    = tid >> 5;
    const int lane = tid & 31;
    const int g    = lane >> 2;
    const int t    = lane & 3;

    const int rowA = q0 + w * 16 + g;
    const size_t vbase = ((size_t)b * NH + h) * HD;   // vT row base (d rows)

    const unsigned ksb = (unsigned)__cvta_generic_to_shared(Ks);
    const unsigned vsb = (unsigned)__cvta_generic_to_shared(Vs);

    auto loadKV = [&](int s, int k0) {
#pragma unroll
        for (int i = 0; i < 2; i++) {
            int idx = tid + i * 256;          // 0..511
            int row = idx >> 3, c8 = idx & 7; // 64 rows x 8 chunks
            cp16(ksb + (s * KV_SZ + row * TS_H + 4 * c8) * 4,
                 qkvh + (size_t)(b * SEQ + k0 + row) * 2048 + CDIM + h * HD + 8 * c8);
            cp16(vsb + (s * KV_SZ + row * TS_H + 4 * c8) * 4,
                 vT + (vbase + row) * SEQ + k0 + 8 * c8);
        }
    };

    // Q fragments, scaled by 0.125 (power of 2: exact in half)
    unsigned qa[4][4];
    {
        const unsigned* Q0 = (const unsigned*)(qkvh + (size_t)(b * SEQ + rowA) * 2048 + h * HD);
        const unsigned* Q8 = Q0 + 8 * 1024;   // +8 rows (1024 unsigned/row)
        const unsigned sc = h2u(__float2half2_rn(0.125f));
#pragma unroll
        for (int kb = 0; kb < 4; kb++) {
            qa[kb][0] = hmul2u(Q0[kb * 8 + t], sc);
            qa[kb][1] = hmul2u(Q8[kb * 8 + t], sc);
            qa[kb][2] = hmul2u(Q0[kb * 8 + t + 4], sc);
            qa[kb][3] = hmul2u(Q8[kb * 8 + t + 4], sc);
        }
    }

    float O[8][4];
#pragma unroll
    for (int nt = 0; nt < 8; nt++)
#pragma unroll
        for (int i = 0; i < 4; i++) O[nt][i] = 0.f;
    float m0 = -INFINITY, m1 = -INFINITY, l0 = 0.f, l1 = 0.f;

    const int ntiles = (q0 + BQ) >> 6;

    loadKV(0, 0); cp_commit();

    for (int kt = 0; kt < ntiles; kt++) {
        const int k0 = kt << 6;
        asm volatile("cp.async.wait_group 0;\n" ::);
        __syncthreads();
        if (kt + 1 < ntiles) loadKV((kt + 1) & 1, (kt + 1) << 6);
        cp_commit();

        // fully-masked tile for this warp: exact identity update -> skip
        if (k0 > q0 + w * 16 + 15) continue;

        const unsigned* ks_ = Ks + (kt & 1) * KV_SZ;
        const unsigned* vs_ = Vs + (kt & 1) * KV_SZ;

        float S[8][4];
#pragma unroll
        for (int nt = 0; nt < 8; nt++)
#pragma unroll
            for (int i = 0; i < 4; i++) S[nt][i] = 0.f;

#pragma unroll
        for (int kb = 0; kb < 4; kb++) {
#pragma unroll
            for (int nt = 0; nt < 8; nt++) {
                const unsigned* kr = &ks_[(nt * 8 + g) * TS_H];
                mma_f16(S[nt], qa[kb][0], qa[kb][1], qa[kb][2], qa[kb][3],
                        kr[kb * 8 + t], kr[kb * 8 + t + 4]);
            }
        }

        if (k0 + BKV - 1 > q0 + w * 16) {
#pragma unroll
            for (int nt = 0; nt < 8; nt++) {
                int col = k0 + nt * 8 + 2 * t;
                if (col > rowA)         S[nt][0] = -INFINITY;
                if (col + 1 > rowA)     S[nt][1] = -INFINITY;
                if (col > rowA + 8)     S[nt][2] = -INFINITY;
                if (col + 1 > rowA + 8) S[nt][3] = -INFINITY;
            }
        }

        float mt0 = -INFINITY, mt1 = -INFINITY;
#pragma unroll
        for (int nt = 0; nt < 8; nt++) {
            mt0 = fmaxf(mt0, fmaxf(S[nt][0], S[nt][1]));
            mt1 = fmaxf(mt1, fmaxf(S[nt][2], S[nt][3]));
        }
#pragma unroll
        for (int off = 1; off < 4; off <<= 1) {
            mt0 = fmaxf(mt0, __shfl_xor_sync(0xffffffffu, mt0, off));
            mt1 = fmaxf(mt1, __shfl_xor_sync(0xffffffffu, mt1, off));
        }
        float mn0 = fmaxf(m0, mt0), mn1 = fmaxf(m1, mt1);
        float al0 = __expf(m0 - mn0), al1 = __expf(m1 - mn1);
        m0 = mn0; m1 = mn1;

        float ls0 = 0.f, ls1 = 0.f;
        unsigned* p0 = &Ps[(w * 16 + g) * TS_H];
        unsigned* p1 = p0 + 8 * TS_H;
#pragma unroll
        for (int nt = 0; nt < 8; nt++) {
            float e00 = __expf(S[nt][0] - mn0);
            float e01 = __expf(S[nt][1] - mn0);
            float e10 = __expf(S[nt][2] - mn1);
            float e11 = __expf(S[nt][3] - mn1);
            ls0 += e00 + e01;
            ls1 += e10 + e11;
            p0[nt * 4 + t] = h2u(__floats2half2_rn(e00, e01));
            p1[nt * 4 + t] = h2u(__floats2half2_rn(e10, e11));
        }
#pragma unroll
        for (int off = 1; off < 4; off <<= 1) {
            ls0 += __shfl_xor_sync(0xffffffffu, ls0, off);
            ls1 += __shfl_xor_sync(0xffffffffu, ls1, off);
        }
        l0 = l0 * al0 + ls0;
        l1 = l1 * al1 + ls1;
#pragma unroll
        for (int nt = 0; nt < 8; nt++) {
            O[nt][0] *= al0; O[nt][1] *= al0;
            O[nt][2] *= al1; O[nt][3] *= al1;
        }
        __syncwarp();

        const unsigned* pr0 = &Ps[(w * 16 + g) * TS_H];
        const unsigned* pr8 = pr0 + 8 * TS_H;
#pragma unroll
        for (int kbv = 0; kbv < 4; kbv++) {
            unsigned pa0 = pr0[kbv * 8 + t];
            unsigned pa1 = pr8[kbv * 8 + t];
            unsigned pa2 = pr0[kbv * 8 + t + 4];
            unsigned pa3 = pr8[kbv * 8 + t + 4];
#pragma unroll
            for (int nt = 0; nt < 8; nt++) {
                const unsigned* vr = &vs_[(nt * 8 + g) * TS_H];
                mma_f16(O[nt], pa0, pa1, pa2, pa3,
                        vr[kbv * 8 + t], vr[kbv * 8 + t + 4]);
            }
        }
    }

    // normalize + write half (proj gemm consumes yh)
    float inv0 = 1.f / l0, inv1 = 1.f / l1;
    __half* y0 = yh + (size_t)(b * SEQ + rowA) * CDIM + h * HD;
    __half* y1 = y0 + (size_t)8 * CDIM;
#pragma unroll
    for (int nt = 0; nt < 8; nt++) {
        *(unsigned*)&y0[nt * 8 + 2 * t] =
            h2u(__floats2half2_rn(O[nt][0] * inv0, O[nt][1] * inv0));
        *(unsigned*)&y1[nt * 8 + 2 * t] =
            h2u(__floats2half2_rn(O[nt][2] * inv1, O[nt][3] * inv1));
    }
}

// ---------------------------------------------------------------------------
extern "C" void kernel_launch(void* const* d_in, const int* in_sizes, int n_in,
                              void* d_out, int out_size)
{
    const float* x      = (const float*)d_in[0];
    const float* W_attn = (const float*)d_in[1];
    const float* b_attn = (const float*)d_in[2];
    const float* W_proj = (const float*)d_in[3];
    const float* b_proj = (const float*)d_in[4];
    float* out = (float*)d_out;

    __half *qkvh, *vT, *xh, *waT, *wpT, *yh;
    cudaGetSymbolAddress((void**)&qkvh, g_qkvh);
    cudaGetSymbolAddress((void**)&vT,   g_vT);
    cudaGetSymbolAddress((void**)&xh,   g_xh);
    cudaGetSymbolAddress((void**)&waT,  g_waT);
    cudaGetSymbolAddress((void**)&wpT,  g_wpT);
    cudaGetSymbolAddress((void**)&yh,   g_yh);

    cudaFuncSetAttribute(gemm_h, cudaFuncAttributeMaxDynamicSharedMemorySize,
                         GEMM_SMEM_H);
    cudaFuncSetAttribute(attn_h, cudaFuncAttributeMaxDynamicSharedMemorySize,
                         ATTN_SMEM_H);

    // 0) pre-pass: x -> half; W_attn, W_proj -> transposed half [N][K]
    {
        int n4x = ROWS * CDIM / 4;
        conv_half<<<(n4x + 255) / 256, 256>>>(x, xh, n4x);
        transpose_h<<<dim3(QKVC / 32, CDIM / 32), dim3(32, 8)>>>(W_attn, waT,
                                                                 CDIM, QKVC);
        transpose_h<<<dim3(CDIM / 32, CDIM / 32), dim3(32, 8)>>>(W_proj, wpT,
                                                                 CDIM, CDIM);
    }

    // 1) qkv = xh @ waT^T + b_attn -> Q|K rows (half) + V transposed (half)
    gemm_h<<<dim3(QKVC / 128, ROWS / 128), 256, GEMM_SMEM_H>>>(
        xh, waT, b_attn, nullptr, qkvh, vT, ROWS, QKVC, CDIM, 1);
    // 2) attention -> yh (half)
    attn_h<<<dim3(SEQ / BQ, NH, BATCH), 256, ATTN_SMEM_H>>>(qkvh, vT, yh);
    // 3) out = yh @ wpT^T + b_proj (fp32 out)
    gemm_h<<<dim3(CDIM / 128, ROWS / 128), 256, GEMM_SMEM_H>>>(
        yh, wpT, b_proj, out, nullptr, nullptr, ROWS, CDIM, CDIM, 0);
}

// round 12
// speedup vs baseline: 2.0888x; 1.3031x over previous
#include <cuda_runtime.h>
#include <cuda_fp16.h>
#include <math.h>

// Problem constants
#define BATCH 4
#define SEQ   2048
#define CDIM  1024
#define NH    16
#define HD    64
#define ROWS  (BATCH*SEQ)      // 8192
#define QKVC  (3*CDIM)         // 3072

// Scratch (allocation-free rule: __device__ globals)
__device__ __half g_qkvh[(size_t)ROWS * 2 * CDIM];     // Q|K rows, half
__device__ __half g_vT[(size_t)BATCH * NH * HD * SEQ]; // V transposed [b][h][d][t]
__device__ __half g_xh[(size_t)ROWS * CDIM];           // x as half
__device__ __half g_waT[(size_t)QKVC * CDIM];          // W_attn^T [N][K]
__device__ __half g_wpT[(size_t)CDIM * CDIM];          // W_proj^T [N][K]
__device__ __half g_yh[(size_t)ROWS * CDIM];           // attn out, half

__device__ __forceinline__ void mma_f16(float c[4], unsigned a0, unsigned a1,
                                        unsigned a2, unsigned a3,
                                        unsigned b0, unsigned b1) {
    asm volatile(
        "mma.sync.aligned.m16n8k16.row.col.f32.f16.f16.f32 "
        "{%0,%1,%2,%3}, {%4,%5,%6,%7}, {%8,%9}, {%0,%1,%2,%3};\n"
        : "+f"(c[0]), "+f"(c[1]), "+f"(c[2]), "+f"(c[3])
        : "r"(a0), "r"(a1), "r"(a2), "r"(a3), "r"(b0), "r"(b1));
}

__device__ __forceinline__ void ldsm4(unsigned& r0, unsigned& r1, unsigned& r2,
                                      unsigned& r3, unsigned addr) {
    asm volatile("ldmatrix.sync.aligned.m8n8.x4.shared.b16 {%0,%1,%2,%3}, [%4];"
                 : "=r"(r0), "=r"(r1), "=r"(r2), "=r"(r3) : "r"(addr));
}

__device__ __forceinline__ void cp16(unsigned smem_addr, const void* gptr) {
    asm volatile("cp.async.cg.shared.global [%0], [%1], 16;\n"
                 :: "r"(smem_addr), "l"(gptr));
}
__device__ __forceinline__ void cp_commit() {
    asm volatile("cp.async.commit_group;\n" ::);
}
__device__ __forceinline__ unsigned h2u(__half2 h) { return *(unsigned*)&h; }
__device__ __forceinline__ unsigned hmul2u(unsigned a, unsigned s) {
    __half2 r = __hmul2(*(__half2*)&a, *(__half2*)&s);
    return *(unsigned*)&r;
}

// ---------------------------------------------------------------------------
// Pre-pass 1: fp32 -> half, contiguous.
// ---------------------------------------------------------------------------
__global__ __launch_bounds__(256)
void conv_half(const float* __restrict__ in, __half* __restrict__ out, int n4)
{
    int i = blockIdx.x * blockDim.x + threadIdx.x;
    if (i < n4) {
        float4 v = ((const float4*)in)[i];
        __half2 lo = __floats2half2_rn(v.x, v.y);
        __half2 hi = __floats2half2_rn(v.z, v.w);
        ((uint2*)out)[i] = make_uint2(h2u(lo), h2u(hi));
    }
}

// ---------------------------------------------------------------------------
// Pre-pass 2: transpose + convert. in [K][N] f32 -> out [N][K] half.
// ---------------------------------------------------------------------------
__global__ __launch_bounds__(256)
void transpose_h(const float* __restrict__ in, __half* __restrict__ out,
                 int K, int N)
{
    __shared__ float t[32][33];
    const int n0 = blockIdx.x * 32, k0 = blockIdx.y * 32;
    const int tx = threadIdx.x, ty = threadIdx.y;
#pragma unroll
    for (int i = 0; i < 4; i++)
        t[ty + 8 * i][tx] = in[(size_t)(k0 + ty + 8 * i) * N + n0 + tx];
    __syncthreads();
#pragma unroll
    for (int i = 0; i < 4; i++)
        out[(size_t)(n0 + ty + 8 * i) * K + k0 + tx] =
            __float2half_rn(t[tx][ty + 8 * i]);
}

// ---------------------------------------------------------------------------
// fp16 tensor-core GEMM + bias. A [M][K] half, Bt [N][K] half (both K-major).
// Block 128x128xBK32, 256 thr = 8 warps (2x4), warp 64x32.
// ldmatrix.x4 fragment loads (stride 20 half2 -> conflict-free),
// 3-stage cp.async, one __syncthreads per k-tile.
// ---------------------------------------------------------------------------
#define BK 32
#define AH_STRIDE 20                 // half2 per row: 16 data + 4 pad
#define AH_SZ (128 * AH_STRIDE)      // unsigned units per stage per operand
#define GEMM_SMEM_H (3 * 2 * AH_SZ * 4)   // 61440 B

__global__ __launch_bounds__(256, 2)
void gemm_h(const __half* __restrict__ A, const __half* __restrict__ Bt,
            const float* __restrict__ bias, float* __restrict__ Cf,
            __half* __restrict__ qkvh, __half* __restrict__ vT,
            int M, int N, int K, int mode)
{
    extern __shared__ unsigned smh[];
    unsigned* Asm = smh;                 // [3][AH_SZ]
    unsigned* Bsm = smh + 3 * AH_SZ;     // [3][AH_SZ]

    const int tid   = threadIdx.x;
    const int wid   = tid >> 5;
    const int lane  = tid & 31;
    const int warpM = wid >> 2;          // 0..1
    const int warpN = wid & 3;           // 0..3
    const int g     = lane >> 2;
    const int t     = lane & 3;

    const int rowBase = blockIdx.y * 128;
    const int colBase = blockIdx.x * 128;

    // loader: 256 threads x (2 A + 2 B) cp16 per stage
    const int ldRow = tid >> 2;          // 0..63 (+64)
    const int ldC   = tid & 3;           // 8-half chunk

    const unsigned sAb = (unsigned)__cvta_generic_to_shared(Asm);
    const unsigned sBb = (unsigned)__cvta_generic_to_shared(Bsm);

    // ldmatrix lane roles
    const int m  = lane >> 3;            // matrix 0..3
    const int mr = lane & 7;             // row within matrix
    const int aRowF = warpM * 64 + (m & 1) * 8 + mr;   // + mt*16
    const int aKsel = (m >> 1) * 4;                    // unsigned units
    const int bColF = warpN * 32 + (m >> 1) * 8 + mr;  // + ntp*16
    const int bKsel = (m & 1) * 4;

    float acc[4][4][4];
#pragma unroll
    for (int mt = 0; mt < 4; mt++)
#pragma unroll
        for (int nt = 0; nt < 4; nt++)
#pragma unroll
            for (int i = 0; i < 4; i++) acc[mt][nt][i] = 0.f;

    const int nTiles = K / BK;

    auto loadTile = [&](int s, int k0) {
#pragma unroll
        for (int i = 0; i < 2; i++) {
            int row = ldRow + i * 64;
            cp16(sAb + (s * AH_SZ + row * AH_STRIDE + 4 * ldC) * 4,
                 A + (size_t)(rowBase + row) * K + k0 + 8 * ldC);
            cp16(sBb + (s * AH_SZ + row * AH_STRIDE + 4 * ldC) * 4,
                 Bt + (size_t)(colBase + row) * K + k0 + 8 * ldC);
        }
    };

    loadTile(0, 0);   cp_commit();
    loadTile(1, BK);  cp_commit();

    for (int kt = 0; kt < nTiles; kt++) {
        asm volatile("cp.async.wait_group 1;\n" ::);
        __syncthreads();
        if (kt + 2 < nTiles) loadTile((kt + 2) % 3, (kt + 2) * BK);
        cp_commit();

        const unsigned aBase = sAb + ((kt % 3) * AH_SZ) * 4;
        const unsigned bBase = sBb + ((kt % 3) * AH_SZ) * 4;

#pragma unroll
        for (int kb = 0; kb < 2; kb++) {
            unsigned af[4][4];
#pragma unroll
            for (int mt = 0; mt < 4; mt++)
                ldsm4(af[mt][0], af[mt][1], af[mt][2], af[mt][3],
                      aBase + ((aRowF + mt * 16) * AH_STRIDE + kb * 8 + aKsel) * 4);
            unsigned bf[4][2];
            ldsm4(bf[0][0], bf[0][1], bf[1][0], bf[1][1],
                  bBase + ((bColF +  0) * AH_STRIDE + kb * 8 + bKsel) * 4);
            ldsm4(bf[2][0], bf[2][1], bf[3][0], bf[3][1],
                  bBase + ((bColF + 16) * AH_STRIDE + kb * 8 + bKsel) * 4);
#pragma unroll
            for (int mt = 0; mt < 4; mt++)
#pragma unroll
                for (int nt = 0; nt < 4; nt++)
                    mma_f16(acc[mt][nt], af[mt][0], af[mt][1], af[mt][2],
                            af[mt][3], bf[nt][0], bf[nt][1]);
        }
    }

#pragma unroll
    for (int mt = 0; mt < 4; mt++) {
        int r0 = rowBase + warpM * 64 + mt * 16 + g;
#pragma unroll
        for (int nt = 0; nt < 4; nt++) {
            int c = colBase + warpN * 32 + nt * 8 + 2 * t;
            float b0 = bias[c], b1 = bias[c + 1];
            float o00 = acc[mt][nt][0] + b0, o01 = acc[mt][nt][1] + b1;
            float o10 = acc[mt][nt][2] + b0, o11 = acc[mt][nt][3] + b1;
            if (mode == 0) {
                *(float2*)&Cf[(size_t)(r0 + 0) * N + c] = make_float2(o00, o01);
                *(float2*)&Cf[(size_t)(r0 + 8) * N + c] = make_float2(o10, o11);
            } else if (c < 2 * CDIM) {
                *(unsigned*)&qkvh[(size_t)(r0 + 0) * 2048 + c] =
                    h2u(__floats2half2_rn(o00, o01));
                *(unsigned*)&qkvh[(size_t)(r0 + 8) * 2048 + c] =
                    h2u(__floats2half2_rn(o10, o11));
            } else {
                int hh = (c - 2 * CDIM) >> 6, d = (c - 2 * CDIM) & 63;
                int bb = r0 >> 11, tt = r0 & 2047;
                size_t rb = ((size_t)bb * NH + hh) * HD;
                vT[(rb + d    ) * SEQ + tt    ] = __float2half_rn(o00);
                vT[(rb + d + 1) * SEQ + tt    ] = __float2half_rn(o01);
                vT[(rb + d    ) * SEQ + tt + 8] = __float2half_rn(o10);
                vT[(rb + d + 1) * SEQ + tt + 8] = __float2half_rn(o11);
            }
        }
    }
}

// ---------------------------------------------------------------------------
// fp16 tensor-core flash attention with ldmatrix fragment loads.
// Stride 36 half2 -> banks 36r mod 32 bijective -> conflict-free ldsm.
// ---------------------------------------------------------------------------
#define BQ 128
#define BKV 64
#define TS_H 36
#define KV_SZ (BKV * TS_H)
#define ATTN_SMEM_H ((2 * KV_SZ + 2 * KV_SZ + BQ * TS_H) * 4)

__global__ __launch_bounds__(256)
void attn_h(const __half* __restrict__ qkvh, const __half* __restrict__ vT,
            __half* __restrict__ yh)
{
    extern __shared__ unsigned smem[];
    unsigned* Ks = smem;                    // [2][KV_SZ]
    unsigned* Vs = smem + 2 * KV_SZ;        // [2][KV_SZ]
    unsigned* Ps = Vs + 2 * KV_SZ;          // [BQ][TS_H]

    const int q0 = blockIdx.x * BQ;
    const int h  = blockIdx.y;
    const int b  = blockIdx.z;

    const int tid  = threadIdx.x;
    const int w    = tid >> 5;
    const int lane = tid & 31;
    const int g    = lane >> 2;
    const int t    = lane & 3;

    const int rowA = q0 + w * 16 + g;
    const size_t vbase = ((size_t)b * NH + h) * HD;

    const unsigned ksb = (unsigned)__cvta_generic_to_shared(Ks);
    const unsigned vsb = (unsigned)__cvta_generic_to_shared(Vs);
    const unsigned psb = (unsigned)__cvta_generic_to_shared(Ps);

    // ldmatrix lane roles (shared by K, V: "row" = n index, contiguous k)
    const int m  = lane >> 3;
    const int mr = lane & 7;
    const int nRowF = (m >> 1) * 8 + mr;    // + ntp*16
    const int nKsel = (m & 1) * 4;
    // P (A-operand) roles
    const int pRowF = w * 16 + (m & 1) * 8 + mr;
    const int pKsel = (m >> 1) * 4;

    auto loadKV = [&](int s, int k0) {
#pragma unroll
        for (int i = 0; i < 2; i++) {
            int idx = tid + i * 256;
            int row = idx >> 3, c8 = idx & 7;
            cp16(ksb + (s * KV_SZ + row * TS_H + 4 * c8) * 4,
                 qkvh + (size_t)(b * SEQ + k0 + row) * 2048 + CDIM + h * HD + 8 * c8);
            cp16(vsb + (s * KV_SZ + row * TS_H + 4 * c8) * 4,
                 vT + (vbase + row) * SEQ + k0 + 8 * c8);
        }
    };

    // Q fragments, scaled by 0.125 (power of 2: exact)
    unsigned qa[4][4];
    {
        const unsigned* Q0 = (const unsigned*)(qkvh + (size_t)(b * SEQ + rowA) * 2048 + h * HD);
        const unsigned* Q8 = Q0 + 8 * 1024;
        const unsigned sc = h2u(__float2half2_rn(0.125f));
#pragma unroll
        for (int kb = 0; kb < 4; kb++) {
            qa[kb][0] = hmul2u(Q0[kb * 8 + t], sc);
            qa[kb][1] = hmul2u(Q8[kb * 8 + t], sc);
            qa[kb][2] = hmul2u(Q0[kb * 8 + t + 4], sc);
            qa[kb][3] = hmul2u(Q8[kb * 8 + t + 4], sc);
        }
    }

    float O[8][4];
#pragma unroll
    for (int nt = 0; nt < 8; nt++)
#pragma unroll
        for (int i = 0; i < 4; i++) O[nt][i] = 0.f;
    float m0 = -INFINITY, m1 = -INFINITY, l0 = 0.f, l1 = 0.f;

    const int ntiles = (q0 + BQ) >> 6;

    loadKV(0, 0); cp_commit();

    for (int kt = 0; kt < ntiles; kt++) {
        const int k0 = kt << 6;
        asm volatile("cp.async.wait_group 0;\n" ::);
        __syncthreads();
        if (kt + 1 < ntiles) loadKV((kt + 1) & 1, (kt + 1) << 6);
        cp_commit();

        if (k0 > q0 + w * 16 + 15) continue;   // exact identity update -> skip

        const unsigned ksB = ksb + ((kt & 1) * KV_SZ) * 4;
        const unsigned vsB = vsb + ((kt & 1) * KV_SZ) * 4;

        float S[8][4];
#pragma unroll
        for (int nt = 0; nt < 8; nt++)
#pragma unroll
            for (int i = 0; i < 4; i++) S[nt][i] = 0.f;

#pragma unroll
        for (int kb = 0; kb < 4; kb++) {
            unsigned kf[8][2];
#pragma unroll
            for (int ntp = 0; ntp < 4; ntp++)
                ldsm4(kf[2*ntp][0], kf[2*ntp][1], kf[2*ntp+1][0], kf[2*ntp+1][1],
                      ksB + ((ntp * 16 + nRowF) * TS_H + kb * 8 + nKsel) * 4);
#pragma unroll
            for (int nt = 0; nt < 8; nt++)
                mma_f16(S[nt], qa[kb][0], qa[kb][1], qa[kb][2], qa[kb][3],
                        kf[nt][0], kf[nt][1]);
        }

        if (k0 + BKV - 1 > q0 + w * 16) {
#pragma unroll
            for (int nt = 0; nt < 8; nt++) {
                int col = k0 + nt * 8 + 2 * t;
                if (col > rowA)         S[nt][0] = -INFINITY;
                if (col + 1 > rowA)     S[nt][1] = -INFINITY;
                if (col > rowA + 8)     S[nt][2] = -INFINITY;
                if (col + 1 > rowA + 8) S[nt][3] = -INFINITY;
            }
        }

        float mt0 = -INFINITY, mt1 = -INFINITY;
#pragma unroll
        for (int nt = 0; nt < 8; nt++) {
            mt0 = fmaxf(mt0, fmaxf(S[nt][0], S[nt][1]));
            mt1 = fmaxf(mt1, fmaxf(S[nt][2], S[nt][3]));
        }
#pragma unroll
        for (int off = 1; off < 4; off <<= 1) {
            mt0 = fmaxf(mt0, __shfl_xor_sync(0xffffffffu, mt0, off));
            mt1 = fmaxf(mt1, __shfl_xor_sync(0xffffffffu, mt1, off));
        }
        float mn0 = fmaxf(m0, mt0), mn1 = fmaxf(m1, mt1);
        float al0 = __expf(m0 - mn0), al1 = __expf(m1 - mn1);
        m0 = mn0; m1 = mn1;

        float ls0 = 0.f, ls1 = 0.f;
        unsigned* p0 = &Ps[(w * 16 + g) * TS_H];
        unsigned* p1 = p0 + 8 * TS_H;
#pragma unroll
        for (int nt = 0; nt < 8; nt++) {
            float e00 = __expf(S[nt][0] - mn0);
            float e01 = __expf(S[nt][1] - mn0);
            float e10 = __expf(S[nt][2] - mn1);
            float e11 = __expf(S[nt][3] - mn1);
            ls0 += e00 + e01;
            ls1 += e10 + e11;
            p0[nt * 4 + t] = h2u(__floats2half2_rn(e00, e01));
            p1[nt * 4 + t] = h2u(__floats2half2_rn(e10, e11));
        }
#pragma unroll
        for (int off = 1; off < 4; off <<= 1) {
            ls0 += __shfl_xor_sync(0xffffffffu, ls0, off);
            ls1 += __shfl_xor_sync(0xffffffffu, ls1, off);
        }
        l0 = l0 * al0 + ls0;
        l1 = l1 * al1 + ls1;
#pragma unroll
        for (int nt = 0; nt < 8; nt++) {
            O[nt][0] *= al0; O[nt][1] *= al0;
            O[nt][2] *= al1; O[nt][3] *= al1;
        }
        __syncwarp();

#pragma unroll
        for (int kbv = 0; kbv < 4; kbv++) {
            unsigned pa[4];
            ldsm4(pa[0], pa[1], pa[2], pa[3],
                  psb + (pRowF * TS_H + kbv * 8 + pKsel) * 4);
            unsigned vf[8][2];
#pragma unroll
            for (int ntp = 0; ntp < 4; ntp++)
                ldsm4(vf[2*ntp][0], vf[2*ntp][1], vf[2*ntp+1][0], vf[2*ntp+1][1],
                      vsB + ((ntp * 16 + nRowF) * TS_H + kbv * 8 + nKsel) * 4);
#pragma unroll
            for (int nt = 0; nt < 8; nt++)
                mma_f16(O[nt], pa[0], pa[1], pa[2], pa[3],
                        vf[nt][0], vf[nt][1]);
        }
    }

    // normalize + write half (proj gemm consumes yh)
    float inv0 = 1.f / l0, inv1 = 1.f / l1;
    __half* y0 = yh + (size_t)(b * SEQ + rowA) * CDIM + h * HD;
    __half* y1 = y0 + (size_t)8 * CDIM;
#pragma unroll
    for (int nt = 0; nt < 8; nt++) {
        *(unsigned*)&y0[nt * 8 + 2 * t] =
            h2u(__floats2half2_rn(O[nt][0] * inv0, O[nt][1] * inv0));
        *(unsigned*)&y1[nt * 8 + 2 * t] =
            h2u(__floats2half2_rn(O[nt][2] * inv1, O[nt][3] * inv1));
    }
}

// ---------------------------------------------------------------------------
extern "C" void kernel_launch(void* const* d_in, const int* in_sizes, int n_in,
                              void* d_out, int out_size)
{
    const float* x      = (const float*)d_in[0];
    const float* W_attn = (const float*)d_in[1];
    const float* b_attn = (const float*)d_in[2];
    const float* W_proj = (const float*)d_in[3];
    const float* b_proj = (const float*)d_in[4];
    float* out = (float*)d_out;

    __half *qkvh, *vT, *xh, *waT, *wpT, *yh;
    cudaGetSymbolAddress((void**)&qkvh, g_qkvh);
    cudaGetSymbolAddress((void**)&vT,   g_vT);
    cudaGetSymbolAddress((void**)&xh,   g_xh);
    cudaGetSymbolAddress((void**)&waT,  g_waT);
    cudaGetSymbolAddress((void**)&wpT,  g_wpT);
    cudaGetSymbolAddress((void**)&yh,   g_yh);

    cudaFuncSetAttribute(gemm_h, cudaFuncAttributeMaxDynamicSharedMemorySize,
                         GEMM_SMEM_H);
    cudaFuncSetAttribute(attn_h, cudaFuncAttributeMaxDynamicSharedMemorySize,
                         ATTN_SMEM_H);

    // 0) pre-pass
    {
        int n4x = ROWS * CDIM / 4;
        conv_half<<<(n4x + 255) / 256, 256>>>(x, xh, n4x);
        transpose_h<<<dim3(QKVC / 32, CDIM / 32), dim3(32, 8)>>>(W_attn, waT,
                                                                 CDIM, QKVC);
        transpose_h<<<dim3(CDIM / 32, CDIM / 32), dim3(32, 8)>>>(W_proj, wpT,
                                                                 CDIM, CDIM);
    }

    // 1) qkv = xh @ waT^T + b_attn -> Q|K rows (half) + V transposed (half)
    gemm_h<<<dim3(QKVC / 128, ROWS / 128), 256, GEMM_SMEM_H>>>(
        xh, waT, b_attn, nullptr, qkvh, vT, ROWS, QKVC, CDIM, 1);
    // 2) attention -> yh (half)
    attn_h<<<dim3(SEQ / BQ, NH, BATCH), 256, ATTN_SMEM_H>>>(qkvh, vT, yh);
    // 3) out = yh @ wpT^T + b_proj (fp32 out)
    gemm_h<<<dim3(CDIM / 128, ROWS / 128), 256, GEMM_SMEM_H>>>(
        yh, wpT, b_proj, out, nullptr, nullptr, ROWS, CDIM, CDIM, 0);
}

// round 14
// speedup vs baseline: 2.1300x; 1.0197x over previous
#include <cuda_runtime.h>
#include <cuda_fp16.h>
#include <math.h>

// Problem constants
#define BATCH 4
#define SEQ   2048
#define CDIM  1024
#define NH    16
#define HD    64
#define ROWS  (BATCH*SEQ)      // 8192
#define QKVC  (3*CDIM)         // 3072

// Scratch (allocation-free rule: __device__ globals)
__device__ __half g_qkvh[(size_t)ROWS * 2 * CDIM];     // Q|K rows, half
__device__ __half g_vT[(size_t)BATCH * NH * HD * SEQ]; // V transposed [b][h][d][t]
__device__ __half g_xh[(size_t)ROWS * CDIM];           // x as half
__device__ __half g_waT[(size_t)QKVC * CDIM];          // W_attn^T [N][K]
__device__ __half g_wpT[(size_t)CDIM * CDIM];          // W_proj^T [N][K]
__device__ __half g_yh[(size_t)ROWS * CDIM];           // attn out, half

__device__ __forceinline__ void mma_f16(float c[4], unsigned a0, unsigned a1,
                                        unsigned a2, unsigned a3,
                                        unsigned b0, unsigned b1) {
    asm volatile(
        "mma.sync.aligned.m16n8k16.row.col.f32.f16.f16.f32 "
        "{%0,%1,%2,%3}, {%4,%5,%6,%7}, {%8,%9}, {%0,%1,%2,%3};\n"
        : "+f"(c[0]), "+f"(c[1]), "+f"(c[2]), "+f"(c[3])
        : "r"(a0), "r"(a1), "r"(a2), "r"(a3), "r"(b0), "r"(b1));
}
__device__ __forceinline__ void ldsm4(unsigned& r0, unsigned& r1, unsigned& r2,
                                      unsigned& r3, unsigned addr) {
    asm volatile("ldmatrix.sync.aligned.m8n8.x4.shared.b16 {%0,%1,%2,%3}, [%4];"
                 : "=r"(r0), "=r"(r1), "=r"(r2), "=r"(r3) : "r"(addr));
}
__device__ __forceinline__ void cp16(unsigned smem_addr, const void* gptr) {
    asm volatile("cp.async.cg.shared.global [%0], [%1], 16;\n"
                 :: "r"(smem_addr), "l"(gptr));
}
__device__ __forceinline__ void cp_commit() {
    asm volatile("cp.async.commit_group;\n" ::);
}
__device__ __forceinline__ unsigned h2u(__half2 h) { return *(unsigned*)&h; }
__device__ __forceinline__ unsigned hmul2u(unsigned a, unsigned s) {
    __half2 r = __hmul2(*(__half2*)&a, *(__half2*)&s);
    return *(unsigned*)&r;
}

// ---------------------------------------------------------------------------
// Pre-pass 1: fp32 -> half, contiguous.
// ---------------------------------------------------------------------------
__global__ __launch_bounds__(256)
void conv_half(const float* __restrict__ in, __half* __restrict__ out, int n4)
{
    int i = blockIdx.x * blockDim.x + threadIdx.x;
    if (i < n4) {
        float4 v = ((const float4*)in)[i];
        __half2 lo = __floats2half2_rn(v.x, v.y);
        __half2 hi = __floats2half2_rn(v.z, v.w);
        ((uint2*)out)[i] = make_uint2(h2u(lo), h2u(hi));
    }
}

// ---------------------------------------------------------------------------
// Pre-pass 2: transpose + convert. in [K][N] f32 -> out [N][K] half.
// ---------------------------------------------------------------------------
__global__ __launch_bounds__(256)
void transpose_h(const float* __restrict__ in, __half* __restrict__ out,
                 int K, int N)
{
    __shared__ float t[32][33];
    const int n0 = blockIdx.x * 32, k0 = blockIdx.y * 32;
    const int tx = threadIdx.x, ty = threadIdx.y;
#pragma unroll
    for (int i = 0; i < 4; i++)
        t[ty + 8 * i][tx] = in[(size_t)(k0 + ty + 8 * i) * N + n0 + tx];
    __syncthreads();
#pragma unroll
    for (int i = 0; i < 4; i++)
        out[(size_t)(n0 + ty + 8 * i) * K + k0 + tx] =
            __float2half_rn(t[tx][ty + 8 * i]);
}

// ---------------------------------------------------------------------------
// fp16 tensor-core GEMM + bias. A [M][K] half, Bt [N][K] half (both K-major).
// Block 128x128xBK64, 256 thr = 8 warps (2x4), warp 64x32.
// ldmatrix.x4 fragment loads (stride 36 u32 -> banks 4r mod 32, conflict-free),
// 3-stage cp.async, ONE __syncthreads per 64-wide k-tile.
// ---------------------------------------------------------------------------
#define BK 64
#define AH_STRIDE 36                 // u32 per row: 32 data + 4 pad
#define AH_SZ (128 * AH_STRIDE)      // u32 units per stage per operand
#define GEMM_SMEM_H (3 * 2 * AH_SZ * 4)   // 110592 B

__global__ __launch_bounds__(256, 2)
void gemm_h(const __half* __restrict__ A, const __half* __restrict__ Bt,
            const float* __restrict__ bias, float* __restrict__ Cf,
            __half* __restrict__ qkvh, __half* __restrict__ vT,
            int M, int N, int K, int mode)
{
    extern __shared__ unsigned smh[];
    unsigned* Asm = smh;                 // [3][AH_SZ]
    unsigned* Bsm = smh + 3 * AH_SZ;     // [3][AH_SZ]

    const int tid   = threadIdx.x;
    const int wid   = tid >> 5;
    const int lane  = tid & 31;
    const int warpM = wid >> 2;          // 0..1
    const int warpN = wid & 3;           // 0..3
    const int g     = lane >> 2;
    const int t     = lane & 3;

    const int rowBase = blockIdx.y * 128;
    const int colBase = blockIdx.x * 128;

    // loader: 1024 16B-chunks per operand per stage; 4 each per thread
    const int ldRow = tid >> 1;          // base pattern (idx>>3 below)

    const unsigned sAb = (unsigned)__cvta_generic_to_shared(Asm);
    const unsigned sBb = (unsigned)__cvta_generic_to_shared(Bsm);

    // ldmatrix lane roles
    const int m  = lane >> 3;            // matrix 0..3
    const int mr = lane & 7;
    const int aRowF = warpM * 64 + (m & 1) * 8 + mr;   // + mt*16
    const int aKsel = (m >> 1) * 4;
    const int bColF = warpN * 32 + (m >> 1) * 8 + mr;  // + ntp*16
    const int bKsel = (m & 1) * 4;

    float acc[4][4][4];
#pragma unroll
    for (int mt = 0; mt < 4; mt++)
#pragma unroll
        for (int nt = 0; nt < 4; nt++)
#pragma unroll
            for (int i = 0; i < 4; i++) acc[mt][nt][i] = 0.f;

    const int nTiles = K / BK;
    (void)ldRow;

    auto loadTile = [&](int s, int k0) {
#pragma unroll
        for (int i = 0; i < 4; i++) {
            int idx = tid + i * 256;          // 0..1023
            int row = idx >> 3, c8 = idx & 7; // 128 rows x 8 chunks
            cp16(sAb + (s * AH_SZ + row * AH_STRIDE + 4 * c8) * 4,
                 A + (size_t)(rowBase + row) * K + k0 + 8 * c8);
            cp16(sBb + (s * AH_SZ + row * AH_STRIDE + 4 * c8) * 4,
                 Bt + (size_t)(colBase + row) * K + k0 + 8 * c8);
        }
    };

    loadTile(0, 0);   cp_commit();
    loadTile(1, BK);  cp_commit();

    for (int kt = 0; kt < nTiles; kt++) {
        asm volatile("cp.async.wait_group 1;\n" ::);
        __syncthreads();
        if (kt + 2 < nTiles) loadTile((kt + 2) % 3, (kt + 2) * BK);
        cp_commit();

        const unsigned aBase = sAb + ((kt % 3) * AH_SZ) * 4;
        const unsigned bBase = sBb + ((kt % 3) * AH_SZ) * 4;

#pragma unroll
        for (int kb = 0; kb < 4; kb++) {
            unsigned af[4][4];
#pragma unroll
            for (int mt = 0; mt < 4; mt++)
                ldsm4(af[mt][0], af[mt][1], af[mt][2], af[mt][3],
                      aBase + ((aRowF + mt * 16) * AH_STRIDE + kb * 8 + aKsel) * 4);
            unsigned bf[4][2];
            ldsm4(bf[0][0], bf[0][1], bf[1][0], bf[1][1],
                  bBase + ((bColF +  0) * AH_STRIDE + kb * 8 + bKsel) * 4);
            ldsm4(bf[2][0], bf[2][1], bf[3][0], bf[3][1],
                  bBase + ((bColF + 16) * AH_STRIDE + kb * 8 + bKsel) * 4);
#pragma unroll
            for (int mt = 0; mt < 4; mt++)
#pragma unroll
                for (int nt = 0; nt < 4; nt++)
                    mma_f16(acc[mt][nt], af[mt][0], af[mt][1], af[mt][2],
                            af[mt][3], bf[nt][0], bf[nt][1]);
        }
    }

#pragma unroll
    for (int mt = 0; mt < 4; mt++) {
        int r0 = rowBase + warpM * 64 + mt * 16 + g;
#pragma unroll
        for (int nt = 0; nt < 4; nt++) {
            int c = colBase + warpN * 32 + nt * 8 + 2 * t;
            float b0 = bias[c], b1 = bias[c + 1];
            float o00 = acc[mt][nt][0] + b0, o01 = acc[mt][nt][1] + b1;
            float o10 = acc[mt][nt][2] + b0, o11 = acc[mt][nt][3] + b1;
            if (mode == 0) {
                *(float2*)&Cf[(size_t)(r0 + 0) * N + c] = make_float2(o00, o01);
                *(float2*)&Cf[(size_t)(r0 + 8) * N + c] = make_float2(o10, o11);
            } else if (c < 2 * CDIM) {
                *(unsigned*)&qkvh[(size_t)(r0 + 0) * 2048 + c] =
                    h2u(__floats2half2_rn(o00, o01));
                *(unsigned*)&qkvh[(size_t)(r0 + 8) * 2048 + c] =
                    h2u(__floats2half2_rn(o10, o11));
            } else {
                int hh = (c - 2 * CDIM) >> 6, d = (c - 2 * CDIM) & 63;
                int bb = r0 >> 11, tt = r0 & 2047;
                size_t rb = ((size_t)bb * NH + hh) * HD;
                vT[(rb + d    ) * SEQ + tt    ] = __float2half_rn(o00);
                vT[(rb + d + 1) * SEQ + tt    ] = __float2half_rn(o01);
                vT[(rb + d    ) * SEQ + tt + 8] = __float2half_rn(o10);
                vT[(rb + d + 1) * SEQ + tt + 8] = __float2half_rn(o11);
            }
        }
    }
}

// ---------------------------------------------------------------------------
// fp16 tensor-core flash attention, ldmatrix fragment loads, 3-stage
// cp.async KV pipeline (prefetch distance 2).
// ---------------------------------------------------------------------------
#define BQ 128
#define BKV 64
#define TS_H 36
#define KV_SZ (BKV * TS_H)
#define ATTN_SMEM_H ((3 * KV_SZ + 3 * KV_SZ + BQ * TS_H) * 4)   // 73728 B

__global__ __launch_bounds__(256)
void attn_h(const __half* __restrict__ qkvh, const __half* __restrict__ vT,
            __half* __restrict__ yh)
{
    extern __shared__ unsigned smem[];
    unsigned* Ks = smem;                    // [3][KV_SZ]
    unsigned* Vs = smem + 3 * KV_SZ;        // [3][KV_SZ]
    unsigned* Ps = Vs + 3 * KV_SZ;          // [BQ][TS_H]

    const int q0 = blockIdx.x * BQ;
    const int h  = blockIdx.y;
    const int b  = blockIdx.z;

    const int tid  = threadIdx.x;
    const int w    = tid >> 5;
    const int lane = tid & 31;
    const int g    = lane >> 2;
    const int t    = lane & 3;

    const int rowA = q0 + w * 16 + g;
    const size_t vbase = ((size_t)b * NH + h) * HD;

    const unsigned ksb = (unsigned)__cvta_generic_to_shared(Ks);
    const unsigned vsb = (unsigned)__cvta_generic_to_shared(Vs);
    const unsigned psb = (unsigned)__cvta_generic_to_shared(Ps);

    const int m  = lane >> 3;
    const int mr = lane & 7;
    const int nRowF = (m >> 1) * 8 + mr;
    const int nKsel = (m & 1) * 4;
    const int pRowF = w * 16 + (m & 1) * 8 + mr;
    const int pKsel = (m >> 1) * 4;

    auto loadKV = [&](int s, int k0) {
#pragma unroll
        for (int i = 0; i < 2; i++) {
            int idx = tid + i * 256;
            int row = idx >> 3, c8 = idx & 7;
            cp16(ksb + (s * KV_SZ + row * TS_H + 4 * c8) * 4,
                 qkvh + (size_t)(b * SEQ + k0 + row) * 2048 + CDIM + h * HD + 8 * c8);
            cp16(vsb + (s * KV_SZ + row * TS_H + 4 * c8) * 4,
                 vT + (vbase + row) * SEQ + k0 + 8 * c8);
        }
    };

    // Q fragments, scaled by 0.125 (power of 2: exact)
    unsigned qa[4][4];
    {
        const unsigned* Q0 = (const unsigned*)(qkvh + (size_t)(b * SEQ + rowA) * 2048 + h * HD);
        const unsigned* Q8 = Q0 + 8 * 1024;
        const unsigned sc = h2u(__float2half2_rn(0.125f));
#pragma unroll
        for (int kb = 0; kb < 4; kb++) {
            qa[kb][0] = hmul2u(Q0[kb * 8 + t], sc);
            qa[kb][1] = hmul2u(Q8[kb * 8 + t], sc);
            qa[kb][2] = hmul2u(Q0[kb * 8 + t + 4], sc);
            qa[kb][3] = hmul2u(Q8[kb * 8 + t + 4], sc);
        }
    }

    float O[8][4];
#pragma unroll
    for (int nt = 0; nt < 8; nt++)
#pragma unroll
        for (int i = 0; i < 4; i++) O[nt][i] = 0.f;
    float m0 = -INFINITY, m1 = -INFINITY, l0 = 0.f, l1 = 0.f;

    const int ntiles = (q0 + BQ) >> 6;     // >= 2 always

    loadKV(0, 0);  cp_commit();
    loadKV(1, 64); cp_commit();

    for (int kt = 0; kt < ntiles; kt++) {
        const int k0 = kt << 6;
        asm volatile("cp.async.wait_group 1;\n" ::);   // tile kt resident
        __syncthreads();
        if (kt + 2 < ntiles) loadKV((kt + 2) % 3, (kt + 2) << 6);
        cp_commit();

        if (k0 > q0 + w * 16 + 15) continue;   // exact identity update -> skip

        const unsigned ksB = ksb + ((kt % 3) * KV_SZ) * 4;
        const unsigned vsB = vsb + ((kt % 3) * KV_SZ) * 4;

        float S[8][4];
#pragma unroll
        for (int nt = 0; nt < 8; nt++)
#pragma unroll
            for (int i = 0; i < 4; i++) S[nt][i] = 0.f;

#pragma unroll
        for (int kb = 0; kb < 4; kb++) {
            unsigned kf[8][2];
#pragma unroll
            for (int ntp = 0; ntp < 4; ntp++)
                ldsm4(kf[2*ntp][0], kf[2*ntp][1], kf[2*ntp+1][0], kf[2*ntp+1][1],
                      ksB + ((ntp * 16 + nRowF) * TS_H + kb * 8 + nKsel) * 4);
#pragma unroll
            for (int nt = 0; nt < 8; nt++)
                mma_f16(S[nt], qa[kb][0], qa[kb][1], qa[kb][2], qa[kb][3],
                        kf[nt][0], kf[nt][1]);
        }

        if (k0 + BKV - 1 > q0 + w * 16) {
#pragma unroll
            for (int nt = 0; nt < 8; nt++) {
                int col = k0 + nt * 8 + 2 * t;
                if (col > rowA)         S[nt][0] = -INFINITY;
                if (col + 1 > rowA)     S[nt][1] = -INFINITY;
                if (col > rowA + 8)     S[nt][2] = -INFINITY;
                if (col + 1 > rowA + 8) S[nt][3] = -INFINITY;
            }
        }

        float mt0 = -INFINITY, mt1 = -INFINITY;
#pragma unroll
        for (int nt = 0; nt < 8; nt++) {
            mt0 = fmaxf(mt0, fmaxf(S[nt][0], S[nt][1]));
            mt1 = fmaxf(mt1, fmaxf(S[nt][2], S[nt][3]));
        }
#pragma unroll
        for (int off = 1; off < 4; off <<= 1) {
            mt0 = fmaxf(mt0, __shfl_xor_sync(0xffffffffu, mt0, off));
            mt1 = fmaxf(mt1, __shfl_xor_sync(0xffffffffu, mt1, off));
        }
        float mn0 = fmaxf(m0, mt0), mn1 = fmaxf(m1, mt1);
        float al0 = __expf(m0 - mn0), al1 = __expf(m1 - mn1);
        m0 = mn0; m1 = mn1;

        float ls0 = 0.f, ls1 = 0.f;
        unsigned* p0 = &Ps[(w * 16 + g) * TS_H];
        unsigned* p1 = p0 + 8 * TS_H;
#pragma unroll
        for (int nt = 0; nt < 8; nt++) {
            float e00 = __expf(S[nt][0] - mn0);
            float e01 = __expf(S[nt][1] - mn0);
            float e10 = __expf(S[nt][2] - mn1);
            float e11 = __expf(S[nt][3] - mn1);
            ls0 += e00 + e01;
            ls1 += e10 + e11;
            p0[nt * 4 + t] = h2u(__floats2half2_rn(e00, e01));
            p1[nt * 4 + t] = h2u(__floats2half2_rn(e10, e11));
        }
#pragma unroll
        for (int off = 1; off < 4; off <<= 1) {
            ls0 += __shfl_xor_sync(0xffffffffu, ls0, off);
            ls1 += __shfl_xor_sync(0xffffffffu, ls1, off);
        }
        l0 = l0 * al0 + ls0;
        l1 = l1 * al1 + ls1;
#pragma unroll
        for (int nt = 0; nt < 8; nt++) {
            O[nt][0] *= al0; O[nt][1] *= al0;
            O[nt][2] *= al1; O[nt][3] *= al1;
        }
        __syncwarp();

#pragma unroll
        for (int kbv = 0; kbv < 4; kbv++) {
            unsigned pa[4];
            ldsm4(pa[0], pa[1], pa[2], pa[3],
                  psb + (pRowF * TS_H + kbv * 8 + pKsel) * 4);
            unsigned vf[8][2];
#pragma unroll
            for (int ntp = 0; ntp < 4; ntp++)
                ldsm4(vf[2*ntp][0], vf[2*ntp][1], vf[2*ntp+1][0], vf[2*ntp+1][1],
                      vsB + ((ntp * 16 + nRowF) * TS_H + kbv * 8 + nKsel) * 4);
#pragma unroll
            for (int nt = 0; nt < 8; nt++)
                mma_f16(O[nt], pa[0], pa[1], pa[2], pa[3],
                        vf[nt][0], vf[nt][1]);
        }
    }

    float inv0 = 1.f / l0, inv1 = 1.f / l1;
    __half* y0 = yh + (size_t)(b * SEQ + rowA) * CDIM + h * HD;
    __half* y1 = y0 + (size_t)8 * CDIM;
#pragma unroll
    for (int nt = 0; nt < 8; nt++) {
        *(unsigned*)&y0[nt * 8 + 2 * t] =
            h2u(__floats2half2_rn(O[nt][0] * inv0, O[nt][1] * inv0));
        *(unsigned*)&y1[nt * 8 + 2 * t] =
            h2u(__floats2half2_rn(O[nt][2] * inv1, O[nt][3] * inv1));
    }
}

// ---------------------------------------------------------------------------
extern "C" void kernel_launch(void* const* d_in, const int* in_sizes, int n_in,
                              void* d_out, int out_size)
{
    const float* x      = (const float*)d_in[0];
    const float* W_attn = (const float*)d_in[1];
    const float* b_attn = (const float*)d_in[2];
    const float* W_proj = (const float*)d_in[3];
    const float* b_proj = (const float*)d_in[4];
    float* out = (float*)d_out;

    __half *qkvh, *vT, *xh, *waT, *wpT, *yh;
    cudaGetSymbolAddress((void**)&qkvh, g_qkvh);
    cudaGetSymbolAddress((void**)&vT,   g_vT);
    cudaGetSymbolAddress((void**)&xh,   g_xh);
    cudaGetSymbolAddress((void**)&waT,  g_waT);
    cudaGetSymbolAddress((void**)&wpT,  g_wpT);
    cudaGetSymbolAddress((void**)&yh,   g_yh);

    cudaFuncSetAttribute(gemm_h, cudaFuncAttributeMaxDynamicSharedMemorySize,
                         GEMM_SMEM_H);
    cudaFuncSetAttribute(attn_h, cudaFuncAttributeMaxDynamicSharedMemorySize,
                         ATTN_SMEM_H);

    // 0) pre-pass
    {
        int n4x = ROWS * CDIM / 4;
        conv_half<<<(n4x + 255) / 256, 256>>>(x, xh, n4x);
        transpose_h<<<dim3(QKVC / 32, CDIM / 32), dim3(32, 8)>>>(W_attn, waT,
                                                                 CDIM, QKVC);
        transpose_h<<<dim3(CDIM / 32, CDIM / 32), dim3(32, 8)>>>(W_proj, wpT,
                                                                 CDIM, CDIM);
    }

    // 1) qkv = xh @ waT^T + b_attn -> Q|K rows (half) + V transposed (half)
    gemm_h<<<dim3(QKVC / 128, ROWS / 128), 256, GEMM_SMEM_H>>>(
        xh, waT, b_attn, nullptr, qkvh, vT, ROWS, QKVC, CDIM, 1);
    // 2) attention -> yh (half)
    attn_h<<<dim3(SEQ / BQ, NH, BATCH), 256, ATTN_SMEM_H>>>(qkvh, vT, yh);
    // 3) out = yh @ wpT^T + b_proj (fp32 out)
    gemm_h<<<dim3(CDIM / 128, ROWS / 128), 256, GEMM_SMEM_H>>>(
        yh, wpT, b_proj, out, nullptr, nullptr, ROWS, CDIM, CDIM, 0);
}